// round 3
// baseline (speedup 1.0000x reference)
#include <cuda_runtime.h>
#include <math.h>
#include <stdint.h>

#define QLEN 512
#define MLEN 512
#define KLEN 1024          // QLEN + MLEN
#define BSZ 8
#define NH 16
#define DH 64
#define DM 1024
#define HD 1024            // NH*DH
#define DI 4096
#define NLAYER 6
#define VOCAB 32000
#define ATT_SCALE 0.125f   // 1/sqrt(64)
#define NEGV -1e30f

#define NROW (QLEN*BSZ)        // 4096
#define KROW (KLEN*BSZ)        // 8192

// ---------------- scratch (static device globals; no runtime allocation) ---------
// g_big is time-shared: during the layer loop it holds AC [0, SCORE) and BD
// [SCORE, 2*SCORE); after the loop it holds the 4096x32000 logits.
#define SCORE_ELEMS ((size_t)BSZ*NH*QLEN*KLEN)            // 67,108,864 floats
#define LOGIT_ELEMS ((size_t)NROW*VOCAB)                  // 131,072,000 floats
#define BIG_ELEMS   (2*SCORE_ELEMS)                       // 134,217,728 floats
static_assert(BIG_ELEMS >= LOGIT_ELEMS, "g_big must also fit logits");
__device__ float g_big   [BIG_ELEMS];
__device__ float g_core  [(size_t)NROW*DM];
__device__ float g_xmem  [(size_t)KROW*DM];
__device__ float g_pos   [(size_t)KLEN*DM];
__device__ float g_q     [(size_t)NROW*HD];
__device__ float g_kv    [(size_t)KROW*2*HD];
__device__ float g_rk    [(size_t)KLEN*HD];
__device__ float g_vec   [(size_t)NROW*HD];
__device__ float g_ff    [(size_t)NROW*DI];
__device__ float g_tmp   [(size_t)NROW*DM];

// ---------------- small utility kernels ----------------

__global__ void k_copy4(const float4* __restrict__ src, float4* __restrict__ dst, int n4) {
    int i = blockIdx.x * blockDim.x + threadIdx.x;
    if (i < n4) dst[i] = src[i];
}

// embedding lookup: core[(i*B+b)] = emb_W[data[i*B+b]]
__global__ void k_embed(const int* __restrict__ data, const float* __restrict__ embW,
                        float* __restrict__ core) {
    int r = blockIdx.x;                       // 0..4095
    int tok = data[r];
    const float4* s = (const float4*)(embW + (size_t)tok * DM);
    float4* d = (float4*)(core + (size_t)r * DM);
    d[threadIdx.x] = s[threadIdx.x];          // 256 threads * float4 = 1024 floats
}

// sinusoidal positions: pos[p,d], pos_seq[p] = KLEN-1-p
__global__ void k_pos(float* __restrict__ pos) {
    int p = blockIdx.x;
    int d = blockIdx.y * 256 + threadIdx.x;   // grid (1024,4)
    float ps = (float)(KLEN - 1 - p);
    int idx = (d < DM/2) ? d : (d - DM/2);
    float e = (float)(2 * idx) / (float)DM;
    float inv = powf(10000.0f, -e);
    float v = ps * inv;
    pos[(size_t)p * DM + d] = (d < DM/2) ? sinf(v) : cosf(v);
}

// ---------------- SGEMM NN: C[M,N] = A[M,K] @ B[K,N] (+bias)(+relu) -------------
// 128x128 tile, BK=8, 256 threads, 8x8 micro-tile. Requires M%128==0, N%128==0, K%8==0.
__global__ void __launch_bounds__(256)
k_sgemm_nn(const float* __restrict__ A, const float* __restrict__ B,
           const float* __restrict__ bias, float* __restrict__ C,
           int M, int N, int K, int relu) {
    __shared__ float As[8][128];
    __shared__ float Bs[8][128];
    int tid = threadIdx.x;
    int bx = blockIdx.x, by = blockIdx.y;
    const float* Ab = A + (size_t)by * 128 * K;
    const float* Bb = B + (size_t)bx * 128;
    float* Cb = C + (size_t)by * 128 * N + (size_t)bx * 128;
    int arow = tid >> 1, acol = (tid & 1) << 2;
    int brow = tid >> 5, bcol = (tid & 31) << 2;
    int tx = tid & 15, ty = tid >> 4;
    float acc[8][8];
#pragma unroll
    for (int r = 0; r < 8; r++)
#pragma unroll
        for (int c = 0; c < 8; c++) acc[r][c] = 0.f;

    for (int k0 = 0; k0 < K; k0 += 8) {
        float4 a4 = *(const float4*)(Ab + (size_t)arow * K + k0 + acol);
        As[acol + 0][arow] = a4.x;
        As[acol + 1][arow] = a4.y;
        As[acol + 2][arow] = a4.z;
        As[acol + 3][arow] = a4.w;
        float4 b4 = *(const float4*)(Bb + (size_t)(k0 + brow) * N + bcol);
        *(float4*)&Bs[brow][bcol] = b4;
        __syncthreads();
#pragma unroll
        for (int k = 0; k < 8; k++) {
            float4 a0 = *(float4*)&As[k][ty * 8];
            float4 a1 = *(float4*)&As[k][ty * 8 + 4];
            float4 b0 = *(float4*)&Bs[k][tx * 8];
            float4 b1 = *(float4*)&Bs[k][tx * 8 + 4];
            float ar[8] = {a0.x,a0.y,a0.z,a0.w,a1.x,a1.y,a1.z,a1.w};
            float br[8] = {b0.x,b0.y,b0.z,b0.w,b1.x,b1.y,b1.z,b1.w};
#pragma unroll
            for (int r = 0; r < 8; r++)
#pragma unroll
                for (int c = 0; c < 8; c++) acc[r][c] += ar[r] * br[c];
        }
        __syncthreads();
    }
#pragma unroll
    for (int r = 0; r < 8; r++) {
        int row = ty * 8 + r;
#pragma unroll
        for (int c = 0; c < 8; c++) {
            int col = tx * 8 + c;
            float v = acc[r][c];
            if (bias) v += bias[(size_t)bx * 128 + col];
            if (relu) v = fmaxf(v, 0.f);
            Cb[(size_t)row * N + col] = v;
        }
    }
}

// ---------------- SGEMM NT: C[M,N] = A[M,K] @ B[N,K]^T  (logits) ----------------
__global__ void __launch_bounds__(256)
k_sgemm_nt(const float* __restrict__ A, const float* __restrict__ B,
           float* __restrict__ C, int M, int N, int K) {
    __shared__ float As[8][128];
    __shared__ float Bs[8][128];
    int tid = threadIdx.x;
    int bx = blockIdx.x, by = blockIdx.y;
    const float* Ab = A + (size_t)by * 128 * K;
    const float* Bb = B + (size_t)bx * 128 * K;
    float* Cb = C + (size_t)by * 128 * N + (size_t)bx * 128;
    int arow = tid >> 1, acol = (tid & 1) << 2;
    int bn = tid >> 1, bk = (tid & 1) << 2;
    int tx = tid & 15, ty = tid >> 4;
    float acc[8][8];
#pragma unroll
    for (int r = 0; r < 8; r++)
#pragma unroll
        for (int c = 0; c < 8; c++) acc[r][c] = 0.f;

    for (int k0 = 0; k0 < K; k0 += 8) {
        float4 a4 = *(const float4*)(Ab + (size_t)arow * K + k0 + acol);
        As[acol + 0][arow] = a4.x;
        As[acol + 1][arow] = a4.y;
        As[acol + 2][arow] = a4.z;
        As[acol + 3][arow] = a4.w;
        float4 b4 = *(const float4*)(Bb + (size_t)bn * K + k0 + bk);
        Bs[bk + 0][bn] = b4.x;
        Bs[bk + 1][bn] = b4.y;
        Bs[bk + 2][bn] = b4.z;
        Bs[bk + 3][bn] = b4.w;
        __syncthreads();
#pragma unroll
        for (int k = 0; k < 8; k++) {
            float4 a0 = *(float4*)&As[k][ty * 8];
            float4 a1 = *(float4*)&As[k][ty * 8 + 4];
            float4 b0 = *(float4*)&Bs[k][tx * 8];
            float4 b1 = *(float4*)&Bs[k][tx * 8 + 4];
            float ar[8] = {a0.x,a0.y,a0.z,a0.w,a1.x,a1.y,a1.z,a1.w};
            float br[8] = {b0.x,b0.y,b0.z,b0.w,b1.x,b1.y,b1.z,b1.w};
#pragma unroll
            for (int r = 0; r < 8; r++)
#pragma unroll
                for (int c = 0; c < 8; c++) acc[r][c] += ar[r] * br[c];
        }
        __syncthreads();
    }
#pragma unroll
    for (int r = 0; r < 8; r++) {
        int row = ty * 8 + r;
#pragma unroll
        for (int c = 0; c < 8; c++)
            Cb[(size_t)row * N + tx * 8 + c] = acc[r][c];
    }
}

// ---------------- batched attention score: Out[g][i,j] = (Q_i + bias_h) . B_j ----
// g = b*16+h. Q element (i,d) at Q[i*8192 + b*1024 + h*64 + d].
// B element (j,d) at Bm[j*jStride + b*bOffB + h*64 + d].
// Out row-major [512,1024] per g. Tile 64x64, K=64 fully resident.
__global__ void __launch_bounds__(256)
k_attn_score(const float* __restrict__ Q, const float* __restrict__ Bm,
             const float* __restrict__ bias, float* __restrict__ Out,
             int jStride, int bOffB) {
    int g = blockIdx.z;
    int b = g >> 4, h = g & 15;
    const float* Ab = Q + (size_t)b * HD + (size_t)h * DH;
    const float* Bb = Bm + (size_t)b * bOffB + (size_t)h * DH;
    const float* bs = bias + (size_t)h * DH;
    int i0 = blockIdx.y * 64, j0 = blockIdx.x * 64;
    __shared__ float As[64][65];
    __shared__ float Bs[64][65];
    int tid = threadIdx.x;
    for (int t = tid; t < 1024; t += 256) {
        int row = t >> 4, c4 = (t & 15) << 2;
        float4 a = *(const float4*)(Ab + (size_t)(i0 + row) * (BSZ * HD) + c4);
        As[row][c4 + 0] = a.x + bs[c4 + 0];
        As[row][c4 + 1] = a.y + bs[c4 + 1];
        As[row][c4 + 2] = a.z + bs[c4 + 2];
        As[row][c4 + 3] = a.w + bs[c4 + 3];
        float4 v = *(const float4*)(Bb + (size_t)(j0 + row) * jStride + c4);
        Bs[row][c4 + 0] = v.x;
        Bs[row][c4 + 1] = v.y;
        Bs[row][c4 + 2] = v.z;
        Bs[row][c4 + 3] = v.w;
    }
    __syncthreads();
    int tx = tid & 15, ty = tid >> 4;
    float acc[4][4];
#pragma unroll
    for (int r = 0; r < 4; r++)
#pragma unroll
        for (int c = 0; c < 4; c++) acc[r][c] = 0.f;
#pragma unroll 8
    for (int d = 0; d < 64; d++) {
        float ar[4], br[4];
#pragma unroll
        for (int r = 0; r < 4; r++) ar[r] = As[ty * 4 + r][d];
#pragma unroll
        for (int c = 0; c < 4; c++) br[c] = Bs[tx * 4 + c][d];
#pragma unroll
        for (int r = 0; r < 4; r++)
#pragma unroll
            for (int c = 0; c < 4; c++) acc[r][c] += ar[r] * br[c];
    }
    float* O = Out + (size_t)g * QLEN * KLEN;
#pragma unroll
    for (int r = 0; r < 4; r++)
#pragma unroll
        for (int c = 0; c < 4; c++)
            O[(size_t)(i0 + ty * 4 + r) * KLEN + (j0 + tx * 4 + c)] = acc[r][c];
}

// ---------------- fused rel-shift + mask + softmax (row of 1024) -----------------
// S[i,j] = mask(j>i+MLEN) ? NEG : (AC[i,j] + BD[i, j+QLEN-1-i]) * scale; softmax_j.
// Probs written back into AC.
__global__ void __launch_bounds__(256)
k_softmax(float* __restrict__ AC, const float* __restrict__ BD) {
    int g = blockIdx.y, i = blockIdx.x;
    float* ac = AC + (size_t)g * QLEN * KLEN + (size_t)i * KLEN;
    const float* bd = BD + (size_t)g * QLEN * KLEN + (size_t)i * KLEN;
    int tid = threadIdx.x;
    __shared__ float red[256];
    float s[4];
#pragma unroll
    for (int u = 0; u < 4; u++) {
        int j = tid + u * 256;
        bool valid = (j <= i + MLEN);
        s[u] = valid ? (ac[j] + bd[j + (QLEN - 1) - i]) * ATT_SCALE : NEGV;
    }
    float m = fmaxf(fmaxf(s[0], s[1]), fmaxf(s[2], s[3]));
    red[tid] = m;
    __syncthreads();
    for (int o = 128; o > 0; o >>= 1) {
        if (tid < o) red[tid] = fmaxf(red[tid], red[tid + o]);
        __syncthreads();
    }
    float M = red[0];
    __syncthreads();
    float e[4], sum = 0.f;
#pragma unroll
    for (int u = 0; u < 4; u++) {
        e[u] = (s[u] > 0.5f * NEGV) ? expf(s[u] - M) : 0.f;
        sum += e[u];
    }
    red[tid] = sum;
    __syncthreads();
    for (int o = 128; o > 0; o >>= 1) {
        if (tid < o) red[tid] += red[tid + o];
        __syncthreads();
    }
    float inv = 1.f / red[0];
#pragma unroll
    for (int u = 0; u < 4; u++) ac[tid + u * 256] = e[u] * inv;
}

// ---------------- batched P @ V: vec[i,b,h*64+d] = sum_j P[g][i,j] V[j,b,h,d] ----
__global__ void __launch_bounds__(256)
k_attn_pv(const float* __restrict__ P, const float* __restrict__ KV,
          float* __restrict__ vec) {
    int g = blockIdx.y;
    int b = g >> 4, h = g & 15;
    int i0 = blockIdx.x * 64;
    const float* Pb = P + (size_t)g * QLEN * KLEN;
    const float* Vb = KV + (size_t)b * (2 * HD) + HD + (size_t)h * DH;  // (j,d): + j*(BSZ*2*HD)
    __shared__ float Ps[64][65];
    __shared__ float Vs[64][65];
    int tid = threadIdx.x, tx = tid & 15, ty = tid >> 4;
    float acc[4][4];
#pragma unroll
    for (int r = 0; r < 4; r++)
#pragma unroll
        for (int c = 0; c < 4; c++) acc[r][c] = 0.f;

    for (int kt = 0; kt < KLEN; kt += 64) {
        for (int t = tid; t < 1024; t += 256) {
            int row = t >> 4, c4 = (t & 15) << 2;
            float4 p4 = *(const float4*)(Pb + (size_t)(i0 + row) * KLEN + kt + c4);
            Ps[row][c4 + 0] = p4.x; Ps[row][c4 + 1] = p4.y;
            Ps[row][c4 + 2] = p4.z; Ps[row][c4 + 3] = p4.w;
            float4 v4 = *(const float4*)(Vb + (size_t)(kt + row) * (BSZ * 2 * HD) + c4);
            Vs[row][c4 + 0] = v4.x; Vs[row][c4 + 1] = v4.y;
            Vs[row][c4 + 2] = v4.z; Vs[row][c4 + 3] = v4.w;
        }
        __syncthreads();
#pragma unroll 8
        for (int jj = 0; jj < 64; jj++) {
            float ar[4], br[4];
#pragma unroll
            for (int r = 0; r < 4; r++) ar[r] = Ps[ty * 4 + r][jj];
#pragma unroll
            for (int c = 0; c < 4; c++) br[c] = Vs[jj][tx * 4 + c];
#pragma unroll
            for (int r = 0; r < 4; r++)
#pragma unroll
                for (int c = 0; c < 4; c++) acc[r][c] += ar[r] * br[c];
        }
        __syncthreads();
    }
#pragma unroll
    for (int r = 0; r < 4; r++) {
        int i = i0 + ty * 4 + r;
#pragma unroll
        for (int c = 0; c < 4; c++)
            vec[((size_t)i * BSZ + b) * HD + (size_t)h * DH + tx * 4 + c] = acc[r][c];
    }
}

// ---------------- layernorm(residual): out = LN(X + R)*g + b ---------------------
__global__ void __launch_bounds__(256)
k_ln(const float* __restrict__ X, const float* __restrict__ R,
     const float* __restrict__ gw, const float* __restrict__ bw,
     float* __restrict__ out) {
    int r = blockIdx.x;
    int tid = threadIdx.x;
    __shared__ float red[256];
    float x[4];
#pragma unroll
    for (int u = 0; u < 4; u++) {
        int d = tid + u * 256;
        x[u] = X[(size_t)r * DM + d] + R[(size_t)r * DM + d];
    }
    float s = x[0] + x[1] + x[2] + x[3];
    red[tid] = s;
    __syncthreads();
    for (int o = 128; o > 0; o >>= 1) {
        if (tid < o) red[tid] += red[tid + o];
        __syncthreads();
    }
    float mu = red[0] * (1.f / DM);
    __syncthreads();
    float v = 0.f;
#pragma unroll
    for (int u = 0; u < 4; u++) { float dd = x[u] - mu; v += dd * dd; }
    red[tid] = v;
    __syncthreads();
    for (int o = 128; o > 0; o >>= 1) {
        if (tid < o) red[tid] += red[tid + o];
        __syncthreads();
    }
    float rstd = rsqrtf(red[0] * (1.f / DM) + 1e-5f);
#pragma unroll
    for (int u = 0; u < 4; u++) {
        int d = tid + u * 256;
        out[(size_t)r * DM + d] = (x[u] - mu) * rstd * gw[d] + bw[d];
    }
}

// ---------------- loss: -(logit[tgt] - logsumexp(row)) ---------------------------
__global__ void __launch_bounds__(256)
k_loss(const float* __restrict__ logits, const int* __restrict__ target,
       float* __restrict__ out) {
    int r = blockIdx.x;
    int tid = threadIdx.x;
    const float* row = logits + (size_t)r * VOCAB;
    float m = -INFINITY, s = 0.f;
    for (int j = tid; j < VOCAB; j += 256) {
        float v = row[j];
        if (v > m) { s = s * expf(m - v) + 1.f; m = v; }
        else s += expf(v - m);
    }
    __shared__ float sm[256], ss[256];
    sm[tid] = m; ss[tid] = s;
    __syncthreads();
    for (int o = 128; o > 0; o >>= 1) {
        if (tid < o) {
            float m1 = sm[tid], m2 = sm[tid + o];
            float M = fmaxf(m1, m2);
            ss[tid] = ss[tid] * expf(m1 - M) + ss[tid + o] * expf(m2 - M);
            sm[tid] = M;
        }
        __syncthreads();
    }
    if (tid == 0) {
        int tgt = target[r];
        out[r] = sm[0] + logf(ss[0]) - row[tgt];
    }
}

// ---------------- host orchestration ---------------------------------------------

static float* sym(const void* s) {
    void* p = nullptr;
    cudaGetSymbolAddress(&p, s);
    return (float*)p;
}

extern "C" void kernel_launch(void* const* d_in, const int* in_sizes, int n_in,
                              void* d_out, int out_size) {
    const int*   data   = (const int*)  d_in[0];
    const int*   target = (const int*)  d_in[1];
    const float* memory = (const float*)d_in[2];
    const float* embW   = (const float*)d_in[3];
    const float* rwb    = (const float*)d_in[4];
    const float* rrb    = (const float*)d_in[5];
    const float* Wq     = (const float*)d_in[6];
    const float* Wkv    = (const float*)d_in[7];
    const float* Wr     = (const float*)d_in[8];
    const float* Wo     = (const float*)d_in[9];
    const float* W1     = (const float*)d_in[10];
    const float* b1     = (const float*)d_in[11];
    const float* W2     = (const float*)d_in[12];
    const float* b2     = (const float*)d_in[13];
    const float* ln1g   = (const float*)d_in[14];
    const float* ln1b   = (const float*)d_in[15];
    const float* ln2g   = (const float*)d_in[16];
    const float* ln2b   = (const float*)d_in[17];

    float* out = (float*)d_out;
    float* loss_out = out;
    float* mems_out = out + (size_t)QLEN * BSZ;

    float* big  = sym(g_big);
    float* ac   = big;                       // scores/probs (SCORE_ELEMS floats)
    float* bd   = big + SCORE_ELEMS;         // BD scores (SCORE_ELEMS floats)
    float* lg   = big;                       // logits (reuses whole buffer later)
    float* core = sym(g_core);
    float* xmem = sym(g_xmem);
    float* pos  = sym(g_pos);
    float* qb   = sym(g_q);
    float* kvb  = sym(g_kv);
    float* rkb  = sym(g_rk);
    float* vec  = sym(g_vec);
    float* ffb  = sym(g_ff);
    float* tmp  = sym(g_tmp);

    const size_t layerF = (size_t)QLEN * BSZ * DM;      // 4,194,304 floats
    const int copy4 = (int)(layerF / 4);                // 1,048,576 float4

    // Only write new_mems slices that fit inside d_out (defensive: if the
    // harness scores only the loss, out_size will be just QLEN*BSZ).
    const size_t outN = (size_t)out_size;
    const size_t lossN = (size_t)QLEN * BSZ;

    k_embed<<<NROW, 256>>>(data, embW, core);
    k_pos<<<dim3(KLEN, 4), 256>>>(pos);
    // new_mems[0] = word_emb (hids[0]); MEM_LEN == QLEN so new_mems[l] == hids[l]
    if (lossN + layerF <= outN)
        k_copy4<<<copy4 / 256, 256>>>((const float4*)core, (float4*)mems_out, copy4);

    for (int l = 0; l < NLAYER; l++) {
        // x_mem = concat(memory[l], core)
        k_copy4<<<copy4 / 256, 256>>>((const float4*)(memory + (size_t)l * layerF),
                                      (float4*)xmem, copy4);
        k_copy4<<<copy4 / 256, 256>>>((const float4*)core, (float4*)(xmem + layerF), copy4);

        k_sgemm_nn<<<dim3(HD / 128, NROW / 128), 256>>>(
            core, Wq + (size_t)l * DM * HD, nullptr, qb, NROW, HD, DM, 0);
        k_sgemm_nn<<<dim3(2 * HD / 128, KROW / 128), 256>>>(
            xmem, Wkv + (size_t)l * DM * 2 * HD, nullptr, kvb, KROW, 2 * HD, DM, 0);
        k_sgemm_nn<<<dim3(HD / 128, KLEN / 128), 256>>>(
            pos, Wr + (size_t)l * DM * HD, nullptr, rkb, KLEN, HD, DM, 0);

        // AC: B = K part of kv, stride per j = BSZ*2*HD, batch off per b = 2*HD
        k_attn_score<<<dim3(KLEN / 64, QLEN / 64, BSZ * NH), 256>>>(
            qb, kvb, rwb, ac, BSZ * 2 * HD, 2 * HD);
        // BD: B = r_k, stride per p = HD, no b dependence
        k_attn_score<<<dim3(KLEN / 64, QLEN / 64, BSZ * NH), 256>>>(
            qb, rkb, rrb, bd, HD, 0);

        k_softmax<<<dim3(QLEN, BSZ * NH), 256>>>(ac, bd);
        k_attn_pv<<<dim3(QLEN / 64, BSZ * NH), 256>>>(ac, kvb, vec);

        k_sgemm_nn<<<dim3(DM / 128, NROW / 128), 256>>>(
            vec, Wo + (size_t)l * HD * DM, nullptr, tmp, NROW, DM, HD, 0);
        k_ln<<<NROW, 256>>>(core, tmp, ln1g + (size_t)l * DM, ln1b + (size_t)l * DM, core);

        k_sgemm_nn<<<dim3(DI / 128, NROW / 128), 256>>>(
            core, W1 + (size_t)l * DM * DI, b1 + (size_t)l * DI, ffb, NROW, DI, DM, 1);
        k_sgemm_nn<<<dim3(DM / 128, NROW / 128), 256>>>(
            ffb, W2 + (size_t)l * DI * DM, b2 + (size_t)l * DM, tmp, NROW, DM, DI, 0);
        k_ln<<<NROW, 256>>>(core, tmp, ln2g + (size_t)l * DM, ln2b + (size_t)l * DM, core);

        // new_mems[l+1] = core (hids[l+1]); layer 5's output is not stored
        if (l < NLAYER - 1 && lossN + (size_t)(l + 2) * layerF <= outN)
            k_copy4<<<copy4 / 256, 256>>>((const float4*)core,
                                          (float4*)(mems_out + (size_t)(l + 1) * layerF), copy4);
    }

    k_sgemm_nt<<<dim3(VOCAB / 128, NROW / 128), 256>>>(core, embW, lg, NROW, VOCAB, DM);
    k_loss<<<NROW, 256>>>(lg, target, loss_out);
}

// round 4
// speedup vs baseline: 1.3974x; 1.3974x over previous
#include <cuda_runtime.h>
#include <math.h>
#include <stdint.h>
#include <mma.h>

using namespace nvcuda;

#define QLEN 512
#define MLEN 512
#define KLEN 1024          // QLEN + MLEN
#define BSZ 8
#define NH 16
#define DH 64
#define DM 1024
#define HD 1024            // NH*DH
#define DI 4096
#define NLAYER 6
#define VOCAB 32000
#define ATT_SCALE 0.125f   // 1/sqrt(64)
#define NEGV -1e30f

#define NROW (QLEN*BSZ)        // 4096
#define KROW (KLEN*BSZ)        // 8192

// ---------------- scratch (static device globals; no runtime allocation) ---------
#define SCORE_ELEMS ((size_t)BSZ*NH*QLEN*KLEN)            // 67,108,864 floats
#define LOGIT_ELEMS ((size_t)NROW*VOCAB)                  // 131,072,000 floats
#define BIG_ELEMS   (2*SCORE_ELEMS)                       // 134,217,728 floats
static_assert(BIG_ELEMS >= LOGIT_ELEMS, "g_big must also fit logits");
__device__ float g_big   [BIG_ELEMS];
__device__ float g_core  [(size_t)NROW*DM];
__device__ float g_xmem  [(size_t)KROW*DM];
__device__ float g_pos   [(size_t)KLEN*DM];
__device__ float g_q     [(size_t)NROW*HD];
__device__ float g_kv    [(size_t)KROW*2*HD];
__device__ float g_rk    [(size_t)KLEN*HD];
__device__ float g_vec   [(size_t)NROW*HD];
__device__ float g_ff    [(size_t)NROW*DI];
__device__ float g_tmp   [(size_t)NROW*DM];

__device__ __forceinline__ float to_tf32(float x) {
    float y;
    asm("cvt.rna.tf32.f32 %0, %1;" : "=f"(y) : "f"(x));
    return y;
}

typedef wmma::fragment<wmma::matrix_a, 16, 16, 8, wmma::precision::tf32, wmma::col_major> FragA;
typedef wmma::fragment<wmma::matrix_b, 16, 16, 8, wmma::precision::tf32, wmma::row_major> FragB;
typedef wmma::fragment<wmma::accumulator, 16, 16, 8, float> FragC;

// ---------------- small utility kernels ----------------

__global__ void k_copy4(const float4* __restrict__ src, float4* __restrict__ dst, int n4) {
    int i = blockIdx.x * blockDim.x + threadIdx.x;
    if (i < n4) dst[i] = src[i];
}

__global__ void k_embed(const int* __restrict__ data, const float* __restrict__ embW,
                        float* __restrict__ core) {
    int r = blockIdx.x;
    int tok = data[r];
    const float4* s = (const float4*)(embW + (size_t)tok * DM);
    float4* d = (float4*)(core + (size_t)r * DM);
    d[threadIdx.x] = s[threadIdx.x];
}

__global__ void k_pos(float* __restrict__ pos) {
    int p = blockIdx.x;
    int d = blockIdx.y * 256 + threadIdx.x;
    float ps = (float)(KLEN - 1 - p);
    int idx = (d < DM/2) ? d : (d - DM/2);
    float e = (float)(2 * idx) / (float)DM;
    float inv = powf(10000.0f, -e);
    float v = ps * inv;
    pos[(size_t)p * DM + d] = (d < DM/2) ? sinf(v) : cosf(v);
}

// ---------------- unified tf32 WMMA GEMM ----------------------------------------
// C[M,N] = A[M,K] @ B (+bias)(+relu).   bN_K==0: B is [K][N];  bN_K==1: B is [N][K] (NT).
// 128x128 block tile, BK=16, 256 threads = 8 warps of 64x32.
#define LDT 136   // smem row stride (multiple of 4 floats = 16B)
__global__ void __launch_bounds__(256)
k_wgemm(const float* __restrict__ A, const float* __restrict__ B,
        const float* __restrict__ bias, float* __restrict__ C,
        int M, int N, int K, int bN_K, int relu) {
    __shared__ float As[16][LDT];      // As[k][m]  (A col-major for wmma)
    __shared__ float Bs[16][LDT];      // Bs[k][n]
    __shared__ float bias_s[16][LDT];  // broadcast rows of bias (accum init)

    int tid = threadIdx.x;
    int bx = blockIdx.x, by = blockIdx.y;
    int warp = tid >> 5;
    int m_off = (warp >> 2) * 64;      // 0 or 64
    int n_off = (warp & 3) * 32;       // 0,32,64,96

    if (bias) {
        for (int idx = tid; idx < 16 * 128; idx += 256) {
            int r = idx >> 7, n = idx & 127;
            bias_s[r][n] = bias[(size_t)bx * 128 + n];
        }
        __syncthreads();
    }

    FragC c[4][2];
#pragma unroll
    for (int i = 0; i < 4; i++)
#pragma unroll
        for (int j = 0; j < 2; j++) {
            if (bias) wmma::load_matrix_sync(c[i][j], &bias_s[0][n_off + j * 16], LDT,
                                             wmma::mem_row_major);
            else      wmma::fill_fragment(c[i][j], 0.0f);
        }

    for (int k0 = 0; k0 < K; k0 += 16) {
        // load A tile: 128 rows x 16 k, store transposed (k-major)
#pragma unroll
        for (int it = 0; it < 2; it++) {
            int idx = tid + it * 256;            // 0..511
            int row = idx >> 2, kq = (idx & 3) << 2;
            float4 a4 = *(const float4*)(A + (size_t)(by * 128 + row) * K + k0 + kq);
            As[kq + 0][row] = to_tf32(a4.x);
            As[kq + 1][row] = to_tf32(a4.y);
            As[kq + 2][row] = to_tf32(a4.z);
            As[kq + 3][row] = to_tf32(a4.w);
        }
        // load B tile
        if (!bN_K) {
#pragma unroll
            for (int it = 0; it < 2; it++) {
                int idx = tid + it * 256;
                int row = idx >> 5, c4 = (idx & 31) << 2;   // row: k, c4: n
                float4 b4 = *(const float4*)(B + (size_t)(k0 + row) * N + (size_t)bx * 128 + c4);
                Bs[row][c4 + 0] = to_tf32(b4.x);
                Bs[row][c4 + 1] = to_tf32(b4.y);
                Bs[row][c4 + 2] = to_tf32(b4.z);
                Bs[row][c4 + 3] = to_tf32(b4.w);
            }
        } else {
#pragma unroll
            for (int it = 0; it < 2; it++) {
                int idx = tid + it * 256;
                int nrow = idx >> 2, kq = (idx & 3) << 2;
                float4 b4 = *(const float4*)(B + (size_t)(bx * 128 + nrow) * K + k0 + kq);
                Bs[kq + 0][nrow] = to_tf32(b4.x);
                Bs[kq + 1][nrow] = to_tf32(b4.y);
                Bs[kq + 2][nrow] = to_tf32(b4.z);
                Bs[kq + 3][nrow] = to_tf32(b4.w);
            }
        }
        __syncthreads();

#pragma unroll
        for (int ks = 0; ks < 2; ks++) {
            FragA a[4];
            FragB bfr[2];
#pragma unroll
            for (int i = 0; i < 4; i++)
                wmma::load_matrix_sync(a[i], &As[ks * 8][m_off + i * 16], LDT);
#pragma unroll
            for (int j = 0; j < 2; j++)
                wmma::load_matrix_sync(bfr[j], &Bs[ks * 8][n_off + j * 16], LDT);
#pragma unroll
            for (int i = 0; i < 4; i++)
#pragma unroll
                for (int j = 0; j < 2; j++)
                    wmma::mma_sync(c[i][j], a[i], bfr[j], c[i][j]);
        }
        __syncthreads();
    }

#pragma unroll
    for (int i = 0; i < 4; i++)
#pragma unroll
        for (int j = 0; j < 2; j++) {
            if (relu)
#pragma unroll
                for (int e = 0; e < c[i][j].num_elements; e++)
                    c[i][j].x[e] = fmaxf(c[i][j].x[e], 0.0f);
            float* dst = C + (size_t)(by * 128 + m_off + i * 16) * N
                           + (size_t)bx * 128 + n_off + j * 16;
            wmma::store_matrix_sync(dst, c[i][j], N, wmma::mem_row_major);
        }
}

// ---------------- batched attention score (tf32 wmma): Out[g][i,j]=(Q_i+bias_h).B_j
#define LDA 72
__global__ void __launch_bounds__(256)
k_attn_score(const float* __restrict__ Q, const float* __restrict__ Bm,
             const float* __restrict__ bias, float* __restrict__ Out,
             int jStride, int bOffB) {
    int g = blockIdx.z;
    int b = g >> 4, h = g & 15;
    const float* Ab = Q + (size_t)b * HD + (size_t)h * DH;
    const float* Bb = Bm + (size_t)b * bOffB + (size_t)h * DH;
    const float* bs = bias + (size_t)h * DH;
    int i0 = blockIdx.y * 64, j0 = blockIdx.x * 64;
    __shared__ float As[64][LDA];   // As[d][i]
    __shared__ float Bs[64][LDA];   // Bs[d][j]
    int tid = threadIdx.x;
    for (int t = tid; t < 1024; t += 256) {
        int row = t >> 4, c4 = (t & 15) << 2;
        float4 a = *(const float4*)(Ab + (size_t)(i0 + row) * (BSZ * HD) + c4);
        As[c4 + 0][row] = to_tf32(a.x + bs[c4 + 0]);
        As[c4 + 1][row] = to_tf32(a.y + bs[c4 + 1]);
        As[c4 + 2][row] = to_tf32(a.z + bs[c4 + 2]);
        As[c4 + 3][row] = to_tf32(a.w + bs[c4 + 3]);
        float4 v = *(const float4*)(Bb + (size_t)(j0 + row) * jStride + c4);
        Bs[c4 + 0][row] = to_tf32(v.x);
        Bs[c4 + 1][row] = to_tf32(v.y);
        Bs[c4 + 2][row] = to_tf32(v.z);
        Bs[c4 + 3][row] = to_tf32(v.w);
    }
    __syncthreads();

    int warp = tid >> 5;
    int mr = warp & 3;              // m-subtile 0..3
    int nc0 = (warp >> 2) * 2;      // n-subtile pair base
    FragC c[2];
    wmma::fill_fragment(c[0], 0.0f);
    wmma::fill_fragment(c[1], 0.0f);
#pragma unroll
    for (int ks = 0; ks < 8; ks++) {
        FragA a;
        wmma::load_matrix_sync(a, &As[ks * 8][mr * 16], LDA);
#pragma unroll
        for (int t = 0; t < 2; t++) {
            FragB bf;
            wmma::load_matrix_sync(bf, &Bs[ks * 8][(nc0 + t) * 16], LDA);
            wmma::mma_sync(c[t], a, bf, c[t]);
        }
    }
    float* O = Out + (size_t)g * QLEN * KLEN;
#pragma unroll
    for (int t = 0; t < 2; t++)
        wmma::store_matrix_sync(O + (size_t)(i0 + mr * 16) * KLEN + j0 + (nc0 + t) * 16,
                                c[t], KLEN, wmma::mem_row_major);
}

// ---------------- fused rel-shift + mask + softmax (row of 1024) -----------------
__global__ void __launch_bounds__(256)
k_softmax(float* __restrict__ AC, const float* __restrict__ BD) {
    int g = blockIdx.y, i = blockIdx.x;
    float* ac = AC + (size_t)g * QLEN * KLEN + (size_t)i * KLEN;
    const float* bd = BD + (size_t)g * QLEN * KLEN + (size_t)i * KLEN;
    int tid = threadIdx.x;
    __shared__ float red[256];
    float s[4];
#pragma unroll
    for (int u = 0; u < 4; u++) {
        int j = tid + u * 256;
        bool valid = (j <= i + MLEN);
        s[u] = valid ? (ac[j] + bd[j + (QLEN - 1) - i]) * ATT_SCALE : NEGV;
    }
    float m = fmaxf(fmaxf(s[0], s[1]), fmaxf(s[2], s[3]));
    red[tid] = m;
    __syncthreads();
    for (int o = 128; o > 0; o >>= 1) {
        if (tid < o) red[tid] = fmaxf(red[tid], red[tid + o]);
        __syncthreads();
    }
    float M = red[0];
    __syncthreads();
    float e[4], sum = 0.f;
#pragma unroll
    for (int u = 0; u < 4; u++) {
        e[u] = (s[u] > 0.5f * NEGV) ? expf(s[u] - M) : 0.f;
        sum += e[u];
    }
    red[tid] = sum;
    __syncthreads();
    for (int o = 128; o > 0; o >>= 1) {
        if (tid < o) red[tid] += red[tid + o];
        __syncthreads();
    }
    float inv = 1.f / red[0];
#pragma unroll
    for (int u = 0; u < 4; u++) ac[tid + u * 256] = e[u] * inv;
}

// ---------------- batched P @ V (tf32 wmma) --------------------------------------
__global__ void __launch_bounds__(256)
k_attn_pv(const float* __restrict__ P, const float* __restrict__ KV,
          float* __restrict__ vec) {
    int g = blockIdx.y;
    int b = g >> 4, h = g & 15;
    int i0 = blockIdx.x * 64;
    const float* Pb = P + (size_t)g * QLEN * KLEN;
    const float* Vb = KV + (size_t)b * (2 * HD) + HD + (size_t)h * DH;
    __shared__ float Ps[64][LDA];   // Ps[j][i]  (A col-major)
    __shared__ float Vs[64][LDA];   // Vs[j][d]  (B row-major)
    int tid = threadIdx.x;
    int warp = tid >> 5;
    int mr = warp & 3;
    int nc0 = (warp >> 2) * 2;
    FragC c[2];
    wmma::fill_fragment(c[0], 0.0f);
    wmma::fill_fragment(c[1], 0.0f);

    for (int kt = 0; kt < KLEN; kt += 64) {
        for (int t = tid; t < 1024; t += 256) {
            int row = t >> 4, c4 = (t & 15) << 2;
            float4 p4 = *(const float4*)(Pb + (size_t)(i0 + row) * KLEN + kt + c4);
            Ps[c4 + 0][row] = to_tf32(p4.x);
            Ps[c4 + 1][row] = to_tf32(p4.y);
            Ps[c4 + 2][row] = to_tf32(p4.z);
            Ps[c4 + 3][row] = to_tf32(p4.w);
            float4 v4 = *(const float4*)(Vb + (size_t)(kt + row) * (BSZ * 2 * HD) + c4);
            Vs[row][c4 + 0] = to_tf32(v4.x);
            Vs[row][c4 + 1] = to_tf32(v4.y);
            Vs[row][c4 + 2] = to_tf32(v4.z);
            Vs[row][c4 + 3] = to_tf32(v4.w);
        }
        __syncthreads();
#pragma unroll
        for (int ks = 0; ks < 8; ks++) {
            FragA a;
            wmma::load_matrix_sync(a, &Ps[ks * 8][mr * 16], LDA);
#pragma unroll
            for (int t = 0; t < 2; t++) {
                FragB bf;
                wmma::load_matrix_sync(bf, &Vs[ks * 8][(nc0 + t) * 16], LDA);
                wmma::mma_sync(c[t], a, bf, c[t]);
            }
        }
        __syncthreads();
    }
#pragma unroll
    for (int t = 0; t < 2; t++) {
        float* dst = vec + ((size_t)(i0 + mr * 16) * BSZ + b) * HD
                         + (size_t)h * DH + (nc0 + t) * 16;
        wmma::store_matrix_sync(dst, c[t], BSZ * HD, wmma::mem_row_major);
    }
}

// ---------------- layernorm(residual): out = LN(X + R)*g + b ---------------------
__global__ void __launch_bounds__(256)
k_ln(const float* __restrict__ X, const float* __restrict__ R,
     const float* __restrict__ gw, const float* __restrict__ bw,
     float* __restrict__ out) {
    int r = blockIdx.x;
    int tid = threadIdx.x;
    __shared__ float red[256];
    float x[4];
#pragma unroll
    for (int u = 0; u < 4; u++) {
        int d = tid + u * 256;
        x[u] = X[(size_t)r * DM + d] + R[(size_t)r * DM + d];
    }
    float s = x[0] + x[1] + x[2] + x[3];
    red[tid] = s;
    __syncthreads();
    for (int o = 128; o > 0; o >>= 1) {
        if (tid < o) red[tid] += red[tid + o];
        __syncthreads();
    }
    float mu = red[0] * (1.f / DM);
    __syncthreads();
    float v = 0.f;
#pragma unroll
    for (int u = 0; u < 4; u++) { float dd = x[u] - mu; v += dd * dd; }
    red[tid] = v;
    __syncthreads();
    for (int o = 128; o > 0; o >>= 1) {
        if (tid < o) red[tid] += red[tid + o];
        __syncthreads();
    }
    float rstd = rsqrtf(red[0] * (1.f / DM) + 1e-5f);
#pragma unroll
    for (int u = 0; u < 4; u++) {
        int d = tid + u * 256;
        out[(size_t)r * DM + d] = (x[u] - mu) * rstd * gw[d] + bw[d];
    }
}

// ---------------- loss: -(logit[tgt] - logsumexp(row)) ---------------------------
__global__ void __launch_bounds__(256)
k_loss(const float* __restrict__ logits, const int* __restrict__ target,
       float* __restrict__ out) {
    int r = blockIdx.x;
    int tid = threadIdx.x;
    const float* row = logits + (size_t)r * VOCAB;
    float m = -INFINITY, s = 0.f;
    for (int j = tid; j < VOCAB; j += 256) {
        float v = row[j];
        if (v > m) { s = s * expf(m - v) + 1.f; m = v; }
        else s += expf(v - m);
    }
    __shared__ float sm[256], ss[256];
    sm[tid] = m; ss[tid] = s;
    __syncthreads();
    for (int o = 128; o > 0; o >>= 1) {
        if (tid < o) {
            float m1 = sm[tid], m2 = sm[tid + o];
            float M = fmaxf(m1, m2);
            ss[tid] = ss[tid] * expf(m1 - M) + ss[tid + o] * expf(m2 - M);
            sm[tid] = M;
        }
        __syncthreads();
    }
    if (tid == 0) {
        int tgt = target[r];
        out[r] = sm[0] + logf(ss[0]) - row[tgt];
    }
}

// ---------------- host orchestration ---------------------------------------------

static float* sym(const void* s) {
    void* p = nullptr;
    cudaGetSymbolAddress(&p, s);
    return (float*)p;
}

extern "C" void kernel_launch(void* const* d_in, const int* in_sizes, int n_in,
                              void* d_out, int out_size) {
    const int*   data   = (const int*)  d_in[0];
    const int*   target = (const int*)  d_in[1];
    const float* memory = (const float*)d_in[2];
    const float* embW   = (const float*)d_in[3];
    const float* rwb    = (const float*)d_in[4];
    const float* rrb    = (const float*)d_in[5];
    const float* Wq     = (const float*)d_in[6];
    const float* Wkv    = (const float*)d_in[7];
    const float* Wr     = (const float*)d_in[8];
    const float* Wo     = (const float*)d_in[9];
    const float* W1     = (const float*)d_in[10];
    const float* b1     = (const float*)d_in[11];
    const float* W2     = (const float*)d_in[12];
    const float* b2     = (const float*)d_in[13];
    const float* ln1g   = (const float*)d_in[14];
    const float* ln1b   = (const float*)d_in[15];
    const float* ln2g   = (const float*)d_in[16];
    const float* ln2b   = (const float*)d_in[17];

    float* out = (float*)d_out;
    float* loss_out = out;
    float* mems_out = out + (size_t)QLEN * BSZ;

    float* big  = sym(g_big);
    float* ac   = big;
    float* bd   = big + SCORE_ELEMS;
    float* lg   = big;
    float* core = sym(g_core);
    float* xmem = sym(g_xmem);
    float* pos  = sym(g_pos);
    float* qb   = sym(g_q);
    float* kvb  = sym(g_kv);
    float* rkb  = sym(g_rk);
    float* vec  = sym(g_vec);
    float* ffb  = sym(g_ff);
    float* tmp  = sym(g_tmp);

    const size_t layerF = (size_t)QLEN * BSZ * DM;
    const int copy4 = (int)(layerF / 4);

    const size_t outN = (size_t)out_size;
    const size_t lossN = (size_t)QLEN * BSZ;

    k_embed<<<NROW, 256>>>(data, embW, core);
    k_pos<<<dim3(KLEN, 4), 256>>>(pos);
    if (lossN + layerF <= outN)
        k_copy4<<<copy4 / 256, 256>>>((const float4*)core, (float4*)mems_out, copy4);

    for (int l = 0; l < NLAYER; l++) {
        k_copy4<<<copy4 / 256, 256>>>((const float4*)(memory + (size_t)l * layerF),
                                      (float4*)xmem, copy4);
        k_copy4<<<copy4 / 256, 256>>>((const float4*)core, (float4*)(xmem + layerF), copy4);

        k_wgemm<<<dim3(HD / 128, NROW / 128), 256>>>(
            core, Wq + (size_t)l * DM * HD, nullptr, qb, NROW, HD, DM, 0, 0);
        k_wgemm<<<dim3(2 * HD / 128, KROW / 128), 256>>>(
            xmem, Wkv + (size_t)l * DM * 2 * HD, nullptr, kvb, KROW, 2 * HD, DM, 0, 0);
        k_wgemm<<<dim3(HD / 128, KLEN / 128), 256>>>(
            pos, Wr + (size_t)l * DM * HD, nullptr, rkb, KLEN, HD, DM, 0, 0);

        k_attn_score<<<dim3(KLEN / 64, QLEN / 64, BSZ * NH), 256>>>(
            qb, kvb, rwb, ac, BSZ * 2 * HD, 2 * HD);
        k_attn_score<<<dim3(KLEN / 64, QLEN / 64, BSZ * NH), 256>>>(
            qb, rkb, rrb, bd, HD, 0);

        k_softmax<<<dim3(QLEN, BSZ * NH), 256>>>(ac, bd);
        k_attn_pv<<<dim3(QLEN / 64, BSZ * NH), 256>>>(ac, kvb, vec);

        k_wgemm<<<dim3(DM / 128, NROW / 128), 256>>>(
            vec, Wo + (size_t)l * HD * DM, nullptr, tmp, NROW, DM, HD, 0, 0);
        k_ln<<<NROW, 256>>>(core, tmp, ln1g + (size_t)l * DM, ln1b + (size_t)l * DM, core);

        k_wgemm<<<dim3(DI / 128, NROW / 128), 256>>>(
            core, W1 + (size_t)l * DM * DI, b1 + (size_t)l * DI, ffb, NROW, DI, DM, 0, 1);
        k_wgemm<<<dim3(DM / 128, NROW / 128), 256>>>(
            ffb, W2 + (size_t)l * DI * DM, b2 + (size_t)l * DM, tmp, NROW, DM, DI, 0, 0);
        k_ln<<<NROW, 256>>>(core, tmp, ln2g + (size_t)l * DM, ln2b + (size_t)l * DM, core);

        if (l < NLAYER - 1 && lossN + (size_t)(l + 2) * layerF <= outN)
            k_copy4<<<copy4 / 256, 256>>>((const float4*)core,
                                          (float4*)(mems_out + (size_t)(l + 1) * layerF), copy4);
    }

    k_wgemm<<<dim3(VOCAB / 128, NROW / 128), 256>>>(
        core, embW, nullptr, lg, NROW, VOCAB, DM, 1, 0);
    k_loss<<<NROW, 256>>>(lg, target, loss_out);
}

// round 5
// speedup vs baseline: 1.6103x; 1.1523x over previous
#include <cuda_runtime.h>
#include <math.h>
#include <stdint.h>
#include <mma.h>

using namespace nvcuda;

#define QLEN 512
#define MLEN 512
#define KLEN 1024          // QLEN + MLEN
#define BSZ 8
#define NH 16
#define DH 64
#define DM 1024
#define HD 1024            // NH*DH
#define DI 4096
#define NLAYER 6
#define VOCAB 32000
#define ATT_SCALE 0.125f   // 1/sqrt(64)
#define NEGV -1e30f

#define NROW (QLEN*BSZ)        // 4096
#define KROW (KLEN*BSZ)        // 8192

// ---------------- scratch (static device globals; no runtime allocation) ---------
#define SCORE_ELEMS ((size_t)BSZ*NH*QLEN*KLEN)            // 67,108,864 floats
#define LOGIT_ELEMS ((size_t)NROW*VOCAB)                  // 131,072,000 floats
#define BIG_ELEMS   (2*SCORE_ELEMS)                       // 134,217,728 floats
static_assert(BIG_ELEMS >= LOGIT_ELEMS, "g_big must also fit logits");
__device__ float g_big   [BIG_ELEMS];
__device__ float g_core  [(size_t)NROW*DM];
__device__ float g_xmem  [(size_t)KROW*DM];
__device__ float g_pos   [(size_t)KLEN*DM];
__device__ float g_q     [(size_t)NROW*HD];
__device__ float g_kv    [(size_t)KROW*2*HD];
__device__ float g_rk    [(size_t)KLEN*HD];
__device__ float g_vec   [(size_t)NROW*HD];
__device__ float g_ff    [(size_t)NROW*DI];
__device__ float g_tmp   [(size_t)NROW*DM];

__device__ __forceinline__ float to_tf32(float x) {
    float y;
    asm("cvt.rna.tf32.f32 %0, %1;" : "=f"(y) : "f"(x));
    return y;
}

typedef wmma::fragment<wmma::matrix_a, 16, 16, 8, wmma::precision::tf32, wmma::col_major> FragA;
typedef wmma::fragment<wmma::matrix_b, 16, 16, 8, wmma::precision::tf32, wmma::row_major> FragB;
typedef wmma::fragment<wmma::accumulator, 16, 16, 8, float> FragC;

// ---------------- small utility kernels ----------------

__global__ void k_copy4(const float4* __restrict__ src, float4* __restrict__ dst, int n4) {
    int i = blockIdx.x * blockDim.x + threadIdx.x;
    if (i < n4) dst[i] = src[i];
}

__global__ void k_embed(const int* __restrict__ data, const float* __restrict__ embW,
                        float* __restrict__ core) {
    int r = blockIdx.x;
    int tok = data[r];
    const float4* s = (const float4*)(embW + (size_t)tok * DM);
    float4* d = (float4*)(core + (size_t)r * DM);
    d[threadIdx.x] = s[threadIdx.x];
}

__global__ void k_pos(float* __restrict__ pos) {
    int p = blockIdx.x;
    int d = blockIdx.y * 256 + threadIdx.x;
    float ps = (float)(KLEN - 1 - p);
    int idx = (d < DM/2) ? d : (d - DM/2);
    float e = (float)(2 * idx) / (float)DM;
    float inv = powf(10000.0f, -e);
    float v = ps * inv;
    pos[(size_t)p * DM + d] = (d < DM/2) ? sinf(v) : cosf(v);
}

// ---------------- unified tf32 WMMA GEMM, double-buffered ------------------------
// C[M,N] = A[M,K] @ B (+bias)(+relu).   bN_K==0: B is [K][N];  bN_K==1: B is [N][K].
// 128x128 block tile, BK=16, 2-stage smem pipeline, 256 threads = 8 warps of 64x32.
#define LDT 136
__global__ void __launch_bounds__(256)
k_wgemm(const float* __restrict__ A, const float* __restrict__ B,
        const float* __restrict__ bias, float* __restrict__ C,
        int M, int N, int K, int bN_K, int relu) {
    __shared__ float As[2][16][LDT];
    __shared__ float Bs[2][16][LDT];
    __shared__ float bias_s[16][LDT];

    int tid = threadIdx.x;
    int bx = blockIdx.x, by = blockIdx.y;
    int warp = tid >> 5;
    int m_off = (warp >> 2) * 64;
    int n_off = (warp & 3) * 32;

    const float* Abase = A + (size_t)by * 128 * K;

    float4 ra[2], rb[2];
    auto ldg = [&](int k0) {
#pragma unroll
        for (int it = 0; it < 2; it++) {
            int idx = tid + it * 256;
            int row = idx >> 2, kq = (idx & 3) << 2;
            ra[it] = *(const float4*)(Abase + (size_t)row * K + k0 + kq);
            if (!bN_K) {
                int brow = idx >> 5, bc = (idx & 31) << 2;
                rb[it] = *(const float4*)(B + (size_t)(k0 + brow) * N + (size_t)bx * 128 + bc);
            } else {
                rb[it] = *(const float4*)(B + (size_t)(bx * 128 + row) * K + k0 + kq);
            }
        }
    };
    auto sts = [&](int s) {
#pragma unroll
        for (int it = 0; it < 2; it++) {
            int idx = tid + it * 256;
            int row = idx >> 2, kq = (idx & 3) << 2;
            As[s][kq + 0][row] = to_tf32(ra[it].x);
            As[s][kq + 1][row] = to_tf32(ra[it].y);
            As[s][kq + 2][row] = to_tf32(ra[it].z);
            As[s][kq + 3][row] = to_tf32(ra[it].w);
            if (!bN_K) {
                int brow = idx >> 5, bc = (idx & 31) << 2;
                Bs[s][brow][bc + 0] = to_tf32(rb[it].x);
                Bs[s][brow][bc + 1] = to_tf32(rb[it].y);
                Bs[s][brow][bc + 2] = to_tf32(rb[it].z);
                Bs[s][brow][bc + 3] = to_tf32(rb[it].w);
            } else {
                Bs[s][kq + 0][row] = to_tf32(rb[it].x);
                Bs[s][kq + 1][row] = to_tf32(rb[it].y);
                Bs[s][kq + 2][row] = to_tf32(rb[it].z);
                Bs[s][kq + 3][row] = to_tf32(rb[it].w);
            }
        }
    };

    if (bias) {
        for (int idx = tid; idx < 16 * 128; idx += 256) {
            int r = idx >> 7, n = idx & 127;
            bias_s[r][n] = bias[(size_t)bx * 128 + n];
        }
    }

    ldg(0);
    sts(0);
    __syncthreads();

    FragC c[4][2];
#pragma unroll
    for (int i = 0; i < 4; i++)
#pragma unroll
        for (int j = 0; j < 2; j++) {
            if (bias) wmma::load_matrix_sync(c[i][j], &bias_s[0][n_off + j * 16], LDT,
                                             wmma::mem_row_major);
            else      wmma::fill_fragment(c[i][j], 0.0f);
        }

    int s = 0;
    for (int k0 = 0; k0 < K; k0 += 16) {
        bool nxt = (k0 + 16) < K;
        if (nxt) ldg(k0 + 16);
#pragma unroll
        for (int ks = 0; ks < 2; ks++) {
            FragA a[4];
            FragB bfr[2];
#pragma unroll
            for (int i = 0; i < 4; i++)
                wmma::load_matrix_sync(a[i], &As[s][ks * 8][m_off + i * 16], LDT);
#pragma unroll
            for (int j = 0; j < 2; j++)
                wmma::load_matrix_sync(bfr[j], &Bs[s][ks * 8][n_off + j * 16], LDT);
#pragma unroll
            for (int i = 0; i < 4; i++)
#pragma unroll
                for (int j = 0; j < 2; j++)
                    wmma::mma_sync(c[i][j], a[i], bfr[j], c[i][j]);
        }
        if (nxt) {
            sts(s ^ 1);
            __syncthreads();
            s ^= 1;
        }
    }

#pragma unroll
    for (int i = 0; i < 4; i++)
#pragma unroll
        for (int j = 0; j < 2; j++) {
            if (relu)
#pragma unroll
                for (int e = 0; e < c[i][j].num_elements; e++)
                    c[i][j].x[e] = fmaxf(c[i][j].x[e], 0.0f);
            float* dst = C + (size_t)(by * 128 + m_off + i * 16) * N
                           + (size_t)bx * 128 + n_off + j * 16;
            wmma::store_matrix_sync(dst, c[i][j], N, wmma::mem_row_major);
        }
}

// ---------------- batched attention score (tf32 wmma) ----------------------------
// mode 0 (AC): skip tiles fully masked (j > i + MLEN for all entries).
// mode 1 (BD): skip tiles never read by the rel-shift gather (j' < 511 - i for all).
#define LDA 72
__global__ void __launch_bounds__(256)
k_attn_score(const float* __restrict__ Q, const float* __restrict__ Bm,
             const float* __restrict__ bias, float* __restrict__ Out,
             int jStride, int bOffB, int mode) {
    int i0 = blockIdx.y * 64, j0 = blockIdx.x * 64;
    if (mode == 0) { if (j0 >= i0 + MLEN + 64) return; }
    else           { if (i0 + j0 < 384) return; }

    int g = blockIdx.z;
    int b = g >> 4, h = g & 15;
    const float* Ab = Q + (size_t)b * HD + (size_t)h * DH;
    const float* Bb = Bm + (size_t)b * bOffB + (size_t)h * DH;
    const float* bs = bias + (size_t)h * DH;
    __shared__ float As[64][LDA];   // As[d][i]
    __shared__ float Bs[64][LDA];   // Bs[d][j]
    int tid = threadIdx.x;
    for (int t = tid; t < 1024; t += 256) {
        int row = t >> 4, c4 = (t & 15) << 2;
        float4 a = *(const float4*)(Ab + (size_t)(i0 + row) * (BSZ * HD) + c4);
        As[c4 + 0][row] = to_tf32(a.x + bs[c4 + 0]);
        As[c4 + 1][row] = to_tf32(a.y + bs[c4 + 1]);
        As[c4 + 2][row] = to_tf32(a.z + bs[c4 + 2]);
        As[c4 + 3][row] = to_tf32(a.w + bs[c4 + 3]);
        float4 v = *(const float4*)(Bb + (size_t)(j0 + row) * jStride + c4);
        Bs[c4 + 0][row] = to_tf32(v.x);
        Bs[c4 + 1][row] = to_tf32(v.y);
        Bs[c4 + 2][row] = to_tf32(v.z);
        Bs[c4 + 3][row] = to_tf32(v.w);
    }
    __syncthreads();

    int warp = tid >> 5;
    int mr = warp & 3;
    int nc0 = (warp >> 2) * 2;
    FragC c[2];
    wmma::fill_fragment(c[0], 0.0f);
    wmma::fill_fragment(c[1], 0.0f);
#pragma unroll
    for (int ks = 0; ks < 8; ks++) {
        FragA a;
        wmma::load_matrix_sync(a, &As[ks * 8][mr * 16], LDA);
#pragma unroll
        for (int t = 0; t < 2; t++) {
            FragB bf;
            wmma::load_matrix_sync(bf, &Bs[ks * 8][(nc0 + t) * 16], LDA);
            wmma::mma_sync(c[t], a, bf, c[t]);
        }
    }
    float* O = Out + (size_t)g * QLEN * KLEN;
#pragma unroll
    for (int t = 0; t < 2; t++)
        wmma::store_matrix_sync(O + (size_t)(i0 + mr * 16) * KLEN + j0 + (nc0 + t) * 16,
                                c[t], KLEN, wmma::mem_row_major);
}

// ---------------- fused rel-shift + mask + softmax (row of 1024) -----------------
__global__ void __launch_bounds__(256)
k_softmax(float* __restrict__ AC, const float* __restrict__ BD) {
    int g = blockIdx.y, i = blockIdx.x;
    float* ac = AC + (size_t)g * QLEN * KLEN + (size_t)i * KLEN;
    const float* bd = BD + (size_t)g * QLEN * KLEN + (size_t)i * KLEN;
    int tid = threadIdx.x;
    __shared__ float red[256];
    float s[4];
#pragma unroll
    for (int u = 0; u < 4; u++) {
        int j = tid + u * 256;
        bool valid = (j <= i + MLEN);
        s[u] = valid ? (ac[j] + bd[j + (QLEN - 1) - i]) * ATT_SCALE : NEGV;
    }
    float m = fmaxf(fmaxf(s[0], s[1]), fmaxf(s[2], s[3]));
    red[tid] = m;
    __syncthreads();
    for (int o = 128; o > 0; o >>= 1) {
        if (tid < o) red[tid] = fmaxf(red[tid], red[tid + o]);
        __syncthreads();
    }
    float M = red[0];
    __syncthreads();
    float e[4], sum = 0.f;
#pragma unroll
    for (int u = 0; u < 4; u++) {
        e[u] = (s[u] > 0.5f * NEGV) ? expf(s[u] - M) : 0.f;
        sum += e[u];
    }
    red[tid] = sum;
    __syncthreads();
    for (int o = 128; o > 0; o >>= 1) {
        if (tid < o) red[tid] += red[tid + o];
        __syncthreads();
    }
    float inv = 1.f / red[0];
#pragma unroll
    for (int u = 0; u < 4; u++) ac[tid + u * 256] = e[u] * inv;
}

// ---------------- batched P @ V (tf32 wmma, double-buffered) ---------------------
__global__ void __launch_bounds__(256)
k_attn_pv(const float* __restrict__ P, const float* __restrict__ KV,
          float* __restrict__ vec) {
    int g = blockIdx.y;
    int b = g >> 4, h = g & 15;
    int i0 = blockIdx.x * 64;
    const float* Pb = P + (size_t)g * QLEN * KLEN;
    const float* Vb = KV + (size_t)b * (2 * HD) + HD + (size_t)h * DH;
    __shared__ float Ps[2][32][LDA];   // Ps[s][j][i]
    __shared__ float Vs[2][32][LDA];   // Vs[s][j][d]
    int tid = threadIdx.x;
    int warp = tid >> 5;
    int mr = warp & 3;
    int nc0 = (warp >> 2) * 2;

    float4 rp[2], rv[2];
    auto ldg = [&](int kt) {
#pragma unroll
        for (int it = 0; it < 2; it++) {
            int idx = tid + it * 256;
            int prow = idx >> 3, pc = (idx & 7) << 2;
            rp[it] = *(const float4*)(Pb + (size_t)(i0 + prow) * KLEN + kt + pc);
            int vrow = idx >> 4, vc = (idx & 15) << 2;
            rv[it] = *(const float4*)(Vb + (size_t)(kt + vrow) * (BSZ * 2 * HD) + vc);
        }
    };
    auto sts = [&](int s) {
#pragma unroll
        for (int it = 0; it < 2; it++) {
            int idx = tid + it * 256;
            int prow = idx >> 3, pc = (idx & 7) << 2;
            Ps[s][pc + 0][prow] = to_tf32(rp[it].x);
            Ps[s][pc + 1][prow] = to_tf32(rp[it].y);
            Ps[s][pc + 2][prow] = to_tf32(rp[it].z);
            Ps[s][pc + 3][prow] = to_tf32(rp[it].w);
            int vrow = idx >> 4, vc = (idx & 15) << 2;
            Vs[s][vrow][vc + 0] = to_tf32(rv[it].x);
            Vs[s][vrow][vc + 1] = to_tf32(rv[it].y);
            Vs[s][vrow][vc + 2] = to_tf32(rv[it].z);
            Vs[s][vrow][vc + 3] = to_tf32(rv[it].w);
        }
    };

    FragC c[2];
    wmma::fill_fragment(c[0], 0.0f);
    wmma::fill_fragment(c[1], 0.0f);

    ldg(0);
    sts(0);
    __syncthreads();
    int s = 0;
    for (int kt = 0; kt < KLEN; kt += 32) {
        bool nxt = (kt + 32) < KLEN;
        if (nxt) ldg(kt + 32);
#pragma unroll
        for (int ks = 0; ks < 4; ks++) {
            FragA a;
            wmma::load_matrix_sync(a, &Ps[s][ks * 8][mr * 16], LDA);
#pragma unroll
            for (int t = 0; t < 2; t++) {
                FragB bf;
                wmma::load_matrix_sync(bf, &Vs[s][ks * 8][(nc0 + t) * 16], LDA);
                wmma::mma_sync(c[t], a, bf, c[t]);
            }
        }
        if (nxt) {
            sts(s ^ 1);
            __syncthreads();
            s ^= 1;
        }
    }
#pragma unroll
    for (int t = 0; t < 2; t++) {
        float* dst = vec + ((size_t)(i0 + mr * 16) * BSZ + b) * HD
                         + (size_t)h * DH + (nc0 + t) * 16;
        wmma::store_matrix_sync(dst, c[t], BSZ * HD, wmma::mem_row_major);
    }
}

// ---------------- layernorm(residual): out = LN(X + R)*g + b ---------------------
__global__ void __launch_bounds__(256)
k_ln(const float* __restrict__ X, const float* __restrict__ R,
     const float* __restrict__ gw, const float* __restrict__ bw,
     float* __restrict__ out) {
    int r = blockIdx.x;
    int tid = threadIdx.x;
    __shared__ float red[256];
    float x[4];
#pragma unroll
    for (int u = 0; u < 4; u++) {
        int d = tid + u * 256;
        x[u] = X[(size_t)r * DM + d] + R[(size_t)r * DM + d];
    }
    float s = x[0] + x[1] + x[2] + x[3];
    red[tid] = s;
    __syncthreads();
    for (int o = 128; o > 0; o >>= 1) {
        if (tid < o) red[tid] += red[tid + o];
        __syncthreads();
    }
    float mu = red[0] * (1.f / DM);
    __syncthreads();
    float v = 0.f;
#pragma unroll
    for (int u = 0; u < 4; u++) { float dd = x[u] - mu; v += dd * dd; }
    red[tid] = v;
    __syncthreads();
    for (int o = 128; o > 0; o >>= 1) {
        if (tid < o) red[tid] += red[tid + o];
        __syncthreads();
    }
    float rstd = rsqrtf(red[0] * (1.f / DM) + 1e-5f);
#pragma unroll
    for (int u = 0; u < 4; u++) {
        int d = tid + u * 256;
        out[(size_t)r * DM + d] = (x[u] - mu) * rstd * gw[d] + bw[d];
    }
}

// ---------------- loss: -(logit[tgt] - logsumexp(row)) ---------------------------
__global__ void __launch_bounds__(256)
k_loss(const float* __restrict__ logits, const int* __restrict__ target,
       float* __restrict__ out) {
    int r = blockIdx.x;
    int tid = threadIdx.x;
    const float* row = logits + (size_t)r * VOCAB;
    float m = -INFINITY, s = 0.f;
    for (int j = tid; j < VOCAB; j += 256) {
        float v = row[j];
        if (v > m) { s = s * expf(m - v) + 1.f; m = v; }
        else s += expf(v - m);
    }
    __shared__ float sm[256], ss[256];
    sm[tid] = m; ss[tid] = s;
    __syncthreads();
    for (int o = 128; o > 0; o >>= 1) {
        if (tid < o) {
            float m1 = sm[tid], m2 = sm[tid + o];
            float M = fmaxf(m1, m2);
            ss[tid] = ss[tid] * expf(m1 - M) + ss[tid + o] * expf(m2 - M);
            sm[tid] = M;
        }
        __syncthreads();
    }
    if (tid == 0) {
        int tgt = target[r];
        out[r] = sm[0] + logf(ss[0]) - row[tgt];
    }
}

// ---------------- host orchestration ---------------------------------------------

static float* sym(const void* s) {
    void* p = nullptr;
    cudaGetSymbolAddress(&p, s);
    return (float*)p;
}

extern "C" void kernel_launch(void* const* d_in, const int* in_sizes, int n_in,
                              void* d_out, int out_size) {
    const int*   data   = (const int*)  d_in[0];
    const int*   target = (const int*)  d_in[1];
    const float* memory = (const float*)d_in[2];
    const float* embW   = (const float*)d_in[3];
    const float* rwb    = (const float*)d_in[4];
    const float* rrb    = (const float*)d_in[5];
    const float* Wq     = (const float*)d_in[6];
    const float* Wkv    = (const float*)d_in[7];
    const float* Wr     = (const float*)d_in[8];
    const float* Wo     = (const float*)d_in[9];
    const float* W1     = (const float*)d_in[10];
    const float* b1     = (const float*)d_in[11];
    const float* W2     = (const float*)d_in[12];
    const float* b2     = (const float*)d_in[13];
    const float* ln1g   = (const float*)d_in[14];
    const float* ln1b   = (const float*)d_in[15];
    const float* ln2g   = (const float*)d_in[16];
    const float* ln2b   = (const float*)d_in[17];

    float* out = (float*)d_out;
    float* loss_out = out;
    float* mems_out = out + (size_t)QLEN * BSZ;

    float* big  = sym(g_big);
    float* ac   = big;
    float* bd   = big + SCORE_ELEMS;
    float* lg   = big;
    float* core = sym(g_core);
    float* xmem = sym(g_xmem);
    float* pos  = sym(g_pos);
    float* qb   = sym(g_q);
    float* kvb  = sym(g_kv);
    float* rkb  = sym(g_rk);
    float* vec  = sym(g_vec);
    float* ffb  = sym(g_ff);
    float* tmp  = sym(g_tmp);

    const size_t layerF = (size_t)QLEN * BSZ * DM;
    const int copy4 = (int)(layerF / 4);

    const size_t outN = (size_t)out_size;
    const size_t lossN = (size_t)QLEN * BSZ;

    k_embed<<<NROW, 256>>>(data, embW, core);
    k_pos<<<dim3(KLEN, 4), 256>>>(pos);
    if (lossN + layerF <= outN)
        k_copy4<<<copy4 / 256, 256>>>((const float4*)core, (float4*)mems_out, copy4);

    for (int l = 0; l < NLAYER; l++) {
        k_copy4<<<copy4 / 256, 256>>>((const float4*)(memory + (size_t)l * layerF),
                                      (float4*)xmem, copy4);
        k_copy4<<<copy4 / 256, 256>>>((const float4*)core, (float4*)(xmem + layerF), copy4);

        k_wgemm<<<dim3(HD / 128, NROW / 128), 256>>>(
            core, Wq + (size_t)l * DM * HD, nullptr, qb, NROW, HD, DM, 0, 0);
        k_wgemm<<<dim3(2 * HD / 128, KROW / 128), 256>>>(
            xmem, Wkv + (size_t)l * DM * 2 * HD, nullptr, kvb, KROW, 2 * HD, DM, 0, 0);
        k_wgemm<<<dim3(HD / 128, KLEN / 128), 256>>>(
            pos, Wr + (size_t)l * DM * HD, nullptr, rkb, KLEN, HD, DM, 0, 0);

        k_attn_score<<<dim3(KLEN / 64, QLEN / 64, BSZ * NH), 256>>>(
            qb, kvb, rwb, ac, BSZ * 2 * HD, 2 * HD, 0);
        k_attn_score<<<dim3(KLEN / 64, QLEN / 64, BSZ * NH), 256>>>(
            qb, rkb, rrb, bd, HD, 0, 1);

        k_softmax<<<dim3(QLEN, BSZ * NH), 256>>>(ac, bd);
        k_attn_pv<<<dim3(QLEN / 64, BSZ * NH), 256>>>(ac, kvb, vec);

        k_wgemm<<<dim3(DM / 128, NROW / 128), 256>>>(
            vec, Wo + (size_t)l * HD * DM, nullptr, tmp, NROW, DM, HD, 0, 0);
        k_ln<<<NROW, 256>>>(core, tmp, ln1g + (size_t)l * DM, ln1b + (size_t)l * DM, core);

        k_wgemm<<<dim3(DI / 128, NROW / 128), 256>>>(
            core, W1 + (size_t)l * DM * DI, b1 + (size_t)l * DI, ffb, NROW, DI, DM, 0, 1);
        k_wgemm<<<dim3(DM / 128, NROW / 128), 256>>>(
            ffb, W2 + (size_t)l * DI * DM, b2 + (size_t)l * DM, tmp, NROW, DM, DI, 0, 0);
        k_ln<<<NROW, 256>>>(core, tmp, ln2g + (size_t)l * DM, ln2b + (size_t)l * DM, core);

        if (l < NLAYER - 1 && lossN + (size_t)(l + 2) * layerF <= outN)
            k_copy4<<<copy4 / 256, 256>>>((const float4*)core,
                                          (float4*)(mems_out + (size_t)(l + 1) * layerF), copy4);
    }

    k_wgemm<<<dim3(VOCAB / 128, NROW / 128), 256>>>(
        core, embW, nullptr, lg, NROW, VOCAB, DM, 1, 0);
    k_loss<<<NROW, 256>>>(lg, target, loss_out);
}

// round 6
// speedup vs baseline: 1.6410x; 1.0191x over previous
#include <cuda_runtime.h>
#include <math.h>
#include <stdint.h>
#include <mma.h>

using namespace nvcuda;

#define QLEN 512
#define MLEN 512
#define KLEN 1024          // QLEN + MLEN
#define BSZ 8
#define NH 16
#define DH 64
#define DM 1024
#define HD 1024            // NH*DH
#define DI 4096
#define NLAYER 6
#define VOCAB 32000
#define ATT_SCALE 0.125f   // 1/sqrt(64)
#define NEGV -1e30f

#define NROW (QLEN*BSZ)        // 4096
#define KROW (KLEN*BSZ)        // 8192

// ---------------- scratch (static device globals; no runtime allocation) ---------
#define SCORE_ELEMS ((size_t)BSZ*NH*QLEN*KLEN)            // 67,108,864 floats
#define LOGIT_ELEMS ((size_t)NROW*VOCAB)                  // 131,072,000 floats
#define BIG_ELEMS   (2*SCORE_ELEMS)                       // 134,217,728 floats
static_assert(BIG_ELEMS >= LOGIT_ELEMS, "g_big must also fit logits");
__device__ float g_big   [BIG_ELEMS];
__device__ float g_core  [(size_t)NROW*DM];
__device__ float g_xmem  [(size_t)KROW*DM];
__device__ float g_pos   [(size_t)KLEN*DM];
__device__ float g_q     [(size_t)NROW*HD];
__device__ float g_kv    [(size_t)KROW*2*HD];
__device__ float g_rk    [(size_t)KLEN*HD];
__device__ float g_vec   [(size_t)NROW*HD];
__device__ float g_ff    [(size_t)NROW*DI];
__device__ float g_tmp   [(size_t)NROW*DM];

__device__ __forceinline__ float to_tf32(float x) {
    float y;
    asm("cvt.rna.tf32.f32 %0, %1;" : "=f"(y) : "f"(x));
    return y;
}

typedef wmma::fragment<wmma::matrix_a, 16, 16, 8, wmma::precision::tf32, wmma::col_major> FragA;
typedef wmma::fragment<wmma::matrix_b, 16, 16, 8, wmma::precision::tf32, wmma::row_major> FragB;
typedef wmma::fragment<wmma::accumulator, 16, 16, 8, float> FragC;

// ---------------- small utility kernels ----------------

__global__ void k_copy4(const float4* __restrict__ src, float4* __restrict__ dst, int n4) {
    int i = blockIdx.x * blockDim.x + threadIdx.x;
    if (i < n4) dst[i] = src[i];
}

__global__ void k_embed(const int* __restrict__ data, const float* __restrict__ embW,
                        float* __restrict__ core) {
    int r = blockIdx.x;
    int tok = data[r];
    const float4* s = (const float4*)(embW + (size_t)tok * DM);
    float4* d = (float4*)(core + (size_t)r * DM);
    d[threadIdx.x] = s[threadIdx.x];
}

__global__ void k_pos(float* __restrict__ pos) {
    int p = blockIdx.x;
    int d = blockIdx.y * 256 + threadIdx.x;
    float ps = (float)(KLEN - 1 - p);
    int idx = (d < DM/2) ? d : (d - DM/2);
    float e = (float)(2 * idx) / (float)DM;
    float inv = powf(10000.0f, -e);
    float v = ps * inv;
    pos[(size_t)p * DM + d] = (d < DM/2) ? sinf(v) : cosf(v);
}

// ---------------- unified tf32 WMMA GEMM, 128x256 tile, double-buffered ----------
// C[M,N] = A[M,K] @ B (+bias)(+relu).   bN_K==0: B is [K][N];  bN_K==1: B is [N][K].
// BK=16, 2-stage dynamic-smem pipeline, 256 threads = 8 warps of 64x64.
#define LDTA 136
#define LDTB 264
#define SM_AS   (2 * 16 * LDTA)                 // floats
#define SM_BS   (2 * 16 * LDTB)
#define SM_BIAS (16 * LDTB)
#define WG_SMEM ((SM_AS + SM_BS + SM_BIAS) * 4) // bytes = 68,096

__global__ void __launch_bounds__(256, 1)
k_wgemm(const float* __restrict__ A, const float* __restrict__ B,
        const float* __restrict__ bias, float* __restrict__ C,
        int M, int N, int K, int bN_K, int relu) {
    extern __shared__ float smem[];
    float (*As)[16][LDTA]  = (float (*)[16][LDTA])smem;
    float (*Bs)[16][LDTB]  = (float (*)[16][LDTB])(smem + SM_AS);
    float (*bias_s)[LDTB]  = (float (*)[LDTB])(smem + SM_AS + SM_BS);

    int tid = threadIdx.x;
    int bx = blockIdx.x, by = blockIdx.y;
    int warp = tid >> 5;
    int m_off = (warp >> 2) * 64;      // 0 or 64
    int n_off = (warp & 3) * 64;       // 0,64,128,192

    const float* Abase = A + (size_t)by * 128 * K;

    float4 ra[2], rb[4];
    auto ldg = [&](int k0) {
#pragma unroll
        for (int it = 0; it < 2; it++) {
            int idx = tid + it * 256;
            int row = idx >> 2, kq = (idx & 3) << 2;
            ra[it] = *(const float4*)(Abase + (size_t)row * K + k0 + kq);
        }
#pragma unroll
        for (int it = 0; it < 4; it++) {
            int idx = tid + it * 256;
            if (!bN_K) {
                int brow = idx >> 6, bc = (idx & 63) << 2;
                rb[it] = *(const float4*)(B + (size_t)(k0 + brow) * N + (size_t)bx * 256 + bc);
            } else {
                int nrow = idx >> 2, kq = (idx & 3) << 2;
                rb[it] = *(const float4*)(B + (size_t)(bx * 256 + nrow) * K + k0 + kq);
            }
        }
    };
    auto sts = [&](int s) {
#pragma unroll
        for (int it = 0; it < 2; it++) {
            int idx = tid + it * 256;
            int row = idx >> 2, kq = (idx & 3) << 2;
            As[s][kq + 0][row] = to_tf32(ra[it].x);
            As[s][kq + 1][row] = to_tf32(ra[it].y);
            As[s][kq + 2][row] = to_tf32(ra[it].z);
            As[s][kq + 3][row] = to_tf32(ra[it].w);
        }
#pragma unroll
        for (int it = 0; it < 4; it++) {
            int idx = tid + it * 256;
            if (!bN_K) {
                int brow = idx >> 6, bc = (idx & 63) << 2;
                Bs[s][brow][bc + 0] = to_tf32(rb[it].x);
                Bs[s][brow][bc + 1] = to_tf32(rb[it].y);
                Bs[s][brow][bc + 2] = to_tf32(rb[it].z);
                Bs[s][brow][bc + 3] = to_tf32(rb[it].w);
            } else {
                int nrow = idx >> 2, kq = (idx & 3) << 2;
                Bs[s][kq + 0][nrow] = to_tf32(rb[it].x);
                Bs[s][kq + 1][nrow] = to_tf32(rb[it].y);
                Bs[s][kq + 2][nrow] = to_tf32(rb[it].z);
                Bs[s][kq + 3][nrow] = to_tf32(rb[it].w);
            }
        }
    };

    if (bias) {
        for (int idx = tid; idx < 16 * 256; idx += 256) {
            int r = idx >> 8, n = idx & 255;
            bias_s[r][n] = bias[(size_t)bx * 256 + n];
        }
    }

    ldg(0);
    sts(0);
    __syncthreads();

    FragC c[4][4];
#pragma unroll
    for (int i = 0; i < 4; i++)
#pragma unroll
        for (int j = 0; j < 4; j++) {
            if (bias) wmma::load_matrix_sync(c[i][j], &bias_s[0][n_off + j * 16], LDTB,
                                             wmma::mem_row_major);
            else      wmma::fill_fragment(c[i][j], 0.0f);
        }

    int s = 0;
    for (int k0 = 0; k0 < K; k0 += 16) {
        bool nxt = (k0 + 16) < K;
        if (nxt) ldg(k0 + 16);
#pragma unroll
        for (int ks = 0; ks < 2; ks++) {
            FragA a[4];
            FragB bfr[4];
#pragma unroll
            for (int i = 0; i < 4; i++)
                wmma::load_matrix_sync(a[i], &As[s][ks * 8][m_off + i * 16], LDTA);
#pragma unroll
            for (int j = 0; j < 4; j++)
                wmma::load_matrix_sync(bfr[j], &Bs[s][ks * 8][n_off + j * 16], LDTB);
#pragma unroll
            for (int i = 0; i < 4; i++)
#pragma unroll
                for (int j = 0; j < 4; j++)
                    wmma::mma_sync(c[i][j], a[i], bfr[j], c[i][j]);
        }
        if (nxt) {
            sts(s ^ 1);
            __syncthreads();
            s ^= 1;
        }
    }

#pragma unroll
    for (int i = 0; i < 4; i++)
#pragma unroll
        for (int j = 0; j < 4; j++) {
            if (relu)
#pragma unroll
                for (int e = 0; e < c[i][j].num_elements; e++)
                    c[i][j].x[e] = fmaxf(c[i][j].x[e], 0.0f);
            float* dst = C + (size_t)(by * 128 + m_off + i * 16) * N
                           + (size_t)bx * 256 + n_off + j * 16;
            wmma::store_matrix_sync(dst, c[i][j], N, wmma::mem_row_major);
        }
}

// ---------------- batched attention score (tf32 wmma) ----------------------------
// mode 0 (AC): skip tiles fully masked. mode 1 (BD): skip tiles never gathered.
#define LDA 72
__global__ void __launch_bounds__(256)
k_attn_score(const float* __restrict__ Q, const float* __restrict__ Bm,
             const float* __restrict__ bias, float* __restrict__ Out,
             int jStride, int bOffB, int mode) {
    int i0 = blockIdx.y * 64, j0 = blockIdx.x * 64;
    if (mode == 0) { if (j0 >= i0 + MLEN + 64) return; }
    else           { if (i0 + j0 < 384) return; }

    int g = blockIdx.z;
    int b = g >> 4, h = g & 15;
    const float* Ab = Q + (size_t)b * HD + (size_t)h * DH;
    const float* Bb = Bm + (size_t)b * bOffB + (size_t)h * DH;
    const float* bs = bias + (size_t)h * DH;
    __shared__ float As[64][LDA];
    __shared__ float Bs[64][LDA];
    int tid = threadIdx.x;
    for (int t = tid; t < 1024; t += 256) {
        int row = t >> 4, c4 = (t & 15) << 2;
        float4 a = *(const float4*)(Ab + (size_t)(i0 + row) * (BSZ * HD) + c4);
        As[c4 + 0][row] = to_tf32(a.x + bs[c4 + 0]);
        As[c4 + 1][row] = to_tf32(a.y + bs[c4 + 1]);
        As[c4 + 2][row] = to_tf32(a.z + bs[c4 + 2]);
        As[c4 + 3][row] = to_tf32(a.w + bs[c4 + 3]);
        float4 v = *(const float4*)(Bb + (size_t)(j0 + row) * jStride + c4);
        Bs[c4 + 0][row] = to_tf32(v.x);
        Bs[c4 + 1][row] = to_tf32(v.y);
        Bs[c4 + 2][row] = to_tf32(v.z);
        Bs[c4 + 3][row] = to_tf32(v.w);
    }
    __syncthreads();

    int warp = tid >> 5;
    int mr = warp & 3;
    int nc0 = (warp >> 2) * 2;
    FragC c[2];
    wmma::fill_fragment(c[0], 0.0f);
    wmma::fill_fragment(c[1], 0.0f);
#pragma unroll
    for (int ks = 0; ks < 8; ks++) {
        FragA a;
        wmma::load_matrix_sync(a, &As[ks * 8][mr * 16], LDA);
#pragma unroll
        for (int t = 0; t < 2; t++) {
            FragB bf;
            wmma::load_matrix_sync(bf, &Bs[ks * 8][(nc0 + t) * 16], LDA);
            wmma::mma_sync(c[t], a, bf, c[t]);
        }
    }
    float* O = Out + (size_t)g * QLEN * KLEN;
#pragma unroll
    for (int t = 0; t < 2; t++)
        wmma::store_matrix_sync(O + (size_t)(i0 + mr * 16) * KLEN + j0 + (nc0 + t) * 16,
                                c[t], KLEN, wmma::mem_row_major);
}

// ---------------- fused rel-shift + mask + softmax (row of 1024) -----------------
__global__ void __launch_bounds__(256)
k_softmax(float* __restrict__ AC, const float* __restrict__ BD) {
    int g = blockIdx.y, i = blockIdx.x;
    float* ac = AC + (size_t)g * QLEN * KLEN + (size_t)i * KLEN;
    const float* bd = BD + (size_t)g * QLEN * KLEN + (size_t)i * KLEN;
    int tid = threadIdx.x;
    __shared__ float red[256];
    float s[4];
#pragma unroll
    for (int u = 0; u < 4; u++) {
        int j = tid + u * 256;
        bool valid = (j <= i + MLEN);
        s[u] = valid ? (ac[j] + bd[j + (QLEN - 1) - i]) * ATT_SCALE : NEGV;
    }
    float m = fmaxf(fmaxf(s[0], s[1]), fmaxf(s[2], s[3]));
    red[tid] = m;
    __syncthreads();
    for (int o = 128; o > 0; o >>= 1) {
        if (tid < o) red[tid] = fmaxf(red[tid], red[tid + o]);
        __syncthreads();
    }
    float M = red[0];
    __syncthreads();
    float e[4], sum = 0.f;
#pragma unroll
    for (int u = 0; u < 4; u++) {
        e[u] = (s[u] > 0.5f * NEGV) ? expf(s[u] - M) : 0.f;
        sum += e[u];
    }
    red[tid] = sum;
    __syncthreads();
    for (int o = 128; o > 0; o >>= 1) {
        if (tid < o) red[tid] += red[tid + o];
        __syncthreads();
    }
    float inv = 1.f / red[0];
#pragma unroll
    for (int u = 0; u < 4; u++) ac[tid + u * 256] = e[u] * inv;
}

// ---------------- batched P @ V (tf32 wmma, double-buffered, masked-tile skip) ---
__global__ void __launch_bounds__(256)
k_attn_pv(const float* __restrict__ P, const float* __restrict__ KV,
          float* __restrict__ vec) {
    int g = blockIdx.y;
    int b = g >> 4, h = g & 15;
    int i0 = blockIdx.x * 64;
    // probs are exactly 0 for j > i + MLEN; tile rows end at i0+63.
    const int kt_end = min(KLEN, i0 + 64 + MLEN);
    const float* Pb = P + (size_t)g * QLEN * KLEN;
    const float* Vb = KV + (size_t)b * (2 * HD) + HD + (size_t)h * DH;
    __shared__ float Ps[2][32][LDA];
    __shared__ float Vs[2][32][LDA];
    int tid = threadIdx.x;
    int warp = tid >> 5;
    int mr = warp & 3;
    int nc0 = (warp >> 2) * 2;

    float4 rp[2], rv[2];
    auto ldg = [&](int kt) {
#pragma unroll
        for (int it = 0; it < 2; it++) {
            int idx = tid + it * 256;
            int prow = idx >> 3, pc = (idx & 7) << 2;
            rp[it] = *(const float4*)(Pb + (size_t)(i0 + prow) * KLEN + kt + pc);
            int vrow = idx >> 4, vc = (idx & 15) << 2;
            rv[it] = *(const float4*)(Vb + (size_t)(kt + vrow) * (BSZ * 2 * HD) + vc);
        }
    };
    auto sts = [&](int s) {
#pragma unroll
        for (int it = 0; it < 2; it++) {
            int idx = tid + it * 256;
            int prow = idx >> 3, pc = (idx & 7) << 2;
            Ps[s][pc + 0][prow] = to_tf32(rp[it].x);
            Ps[s][pc + 1][prow] = to_tf32(rp[it].y);
            Ps[s][pc + 2][prow] = to_tf32(rp[it].z);
            Ps[s][pc + 3][prow] = to_tf32(rp[it].w);
            int vrow = idx >> 4, vc = (idx & 15) << 2;
            Vs[s][vrow][vc + 0] = to_tf32(rv[it].x);
            Vs[s][vrow][vc + 1] = to_tf32(rv[it].y);
            Vs[s][vrow][vc + 2] = to_tf32(rv[it].z);
            Vs[s][vrow][vc + 3] = to_tf32(rv[it].w);
        }
    };

    FragC c[2];
    wmma::fill_fragment(c[0], 0.0f);
    wmma::fill_fragment(c[1], 0.0f);

    ldg(0);
    sts(0);
    __syncthreads();
    int s = 0;
    for (int kt = 0; kt < kt_end; kt += 32) {
        bool nxt = (kt + 32) < kt_end;
        if (nxt) ldg(kt + 32);
#pragma unroll
        for (int ks = 0; ks < 4; ks++) {
            FragA a;
            wmma::load_matrix_sync(a, &Ps[s][ks * 8][mr * 16], LDA);
#pragma unroll
            for (int t = 0; t < 2; t++) {
                FragB bf;
                wmma::load_matrix_sync(bf, &Vs[s][ks * 8][(nc0 + t) * 16], LDA);
                wmma::mma_sync(c[t], a, bf, c[t]);
            }
        }
        if (nxt) {
            sts(s ^ 1);
            __syncthreads();
            s ^= 1;
        }
    }
#pragma unroll
    for (int t = 0; t < 2; t++) {
        float* dst = vec + ((size_t)(i0 + mr * 16) * BSZ + b) * HD
                         + (size_t)h * DH + (nc0 + t) * 16;
        wmma::store_matrix_sync(dst, c[t], BSZ * HD, wmma::mem_row_major);
    }
}

// ---------------- layernorm(residual): out = LN(X + R)*g + b ---------------------
__global__ void __launch_bounds__(256)
k_ln(const float* __restrict__ X, const float* __restrict__ R,
     const float* __restrict__ gw, const float* __restrict__ bw,
     float* __restrict__ out) {
    int r = blockIdx.x;
    int tid = threadIdx.x;
    __shared__ float red[256];
    float x[4];
#pragma unroll
    for (int u = 0; u < 4; u++) {
        int d = tid + u * 256;
        x[u] = X[(size_t)r * DM + d] + R[(size_t)r * DM + d];
    }
    float s = x[0] + x[1] + x[2] + x[3];
    red[tid] = s;
    __syncthreads();
    for (int o = 128; o > 0; o >>= 1) {
        if (tid < o) red[tid] += red[tid + o];
        __syncthreads();
    }
    float mu = red[0] * (1.f / DM);
    __syncthreads();
    float v = 0.f;
#pragma unroll
    for (int u = 0; u < 4; u++) { float dd = x[u] - mu; v += dd * dd; }
    red[tid] = v;
    __syncthreads();
    for (int o = 128; o > 0; o >>= 1) {
        if (tid < o) red[tid] += red[tid + o];
        __syncthreads();
    }
    float rstd = rsqrtf(red[0] * (1.f / DM) + 1e-5f);
#pragma unroll
    for (int u = 0; u < 4; u++) {
        int d = tid + u * 256;
        out[(size_t)r * DM + d] = (x[u] - mu) * rstd * gw[d] + bw[d];
    }
}

// ---------------- loss: -(logit[tgt] - logsumexp(row)) ---------------------------
__global__ void __launch_bounds__(256)
k_loss(const float* __restrict__ logits, const int* __restrict__ target,
       float* __restrict__ out) {
    int r = blockIdx.x;
    int tid = threadIdx.x;
    const float* row = logits + (size_t)r * VOCAB;
    float m = -INFINITY, s = 0.f;
    for (int j = tid; j < VOCAB; j += 256) {
        float v = row[j];
        if (v > m) { s = s * expf(m - v) + 1.f; m = v; }
        else s += expf(v - m);
    }
    __shared__ float sm[256], ss[256];
    sm[tid] = m; ss[tid] = s;
    __syncthreads();
    for (int o = 128; o > 0; o >>= 1) {
        if (tid < o) {
            float m1 = sm[tid], m2 = sm[tid + o];
            float M = fmaxf(m1, m2);
            ss[tid] = ss[tid] * expf(m1 - M) + ss[tid + o] * expf(m2 - M);
            sm[tid] = M;
        }
        __syncthreads();
    }
    if (tid == 0) {
        int tgt = target[r];
        out[r] = sm[0] + logf(ss[0]) - row[tgt];
    }
}

// ---------------- host orchestration ---------------------------------------------

static float* sym(const void* s) {
    void* p = nullptr;
    cudaGetSymbolAddress(&p, s);
    return (float*)p;
}

extern "C" void kernel_launch(void* const* d_in, const int* in_sizes, int n_in,
                              void* d_out, int out_size) {
    const int*   data   = (const int*)  d_in[0];
    const int*   target = (const int*)  d_in[1];
    const float* memory = (const float*)d_in[2];
    const float* embW   = (const float*)d_in[3];
    const float* rwb    = (const float*)d_in[4];
    const float* rrb    = (const float*)d_in[5];
    const float* Wq     = (const float*)d_in[6];
    const float* Wkv    = (const float*)d_in[7];
    const float* Wr     = (const float*)d_in[8];
    const float* Wo     = (const float*)d_in[9];
    const float* W1     = (const float*)d_in[10];
    const float* b1     = (const float*)d_in[11];
    const float* W2     = (const float*)d_in[12];
    const float* b2     = (const float*)d_in[13];
    const float* ln1g   = (const float*)d_in[14];
    const float* ln1b   = (const float*)d_in[15];
    const float* ln2g   = (const float*)d_in[16];
    const float* ln2b   = (const float*)d_in[17];

    float* out = (float*)d_out;
    float* loss_out = out;
    float* mems_out = out + (size_t)QLEN * BSZ;

    float* big  = sym(g_big);
    float* ac   = big;
    float* bd   = big + SCORE_ELEMS;
    float* lg   = big;
    float* core = sym(g_core);
    float* xmem = sym(g_xmem);
    float* pos  = sym(g_pos);
    float* qb   = sym(g_q);
    float* kvb  = sym(g_kv);
    float* rkb  = sym(g_rk);
    float* vec  = sym(g_vec);
    float* ffb  = sym(g_ff);
    float* tmp  = sym(g_tmp);

    cudaFuncSetAttribute(k_wgemm, cudaFuncAttributeMaxDynamicSharedMemorySize, WG_SMEM);

    const size_t layerF = (size_t)QLEN * BSZ * DM;
    const int copy4 = (int)(layerF / 4);

    const size_t outN = (size_t)out_size;
    const size_t lossN = (size_t)QLEN * BSZ;

    k_embed<<<NROW, 256>>>(data, embW, core);
    k_pos<<<dim3(KLEN, 4), 256>>>(pos);
    if (lossN + layerF <= outN)
        k_copy4<<<copy4 / 256, 256>>>((const float4*)core, (float4*)mems_out, copy4);

    for (int l = 0; l < NLAYER; l++) {
        k_copy4<<<copy4 / 256, 256>>>((const float4*)(memory + (size_t)l * layerF),
                                      (float4*)xmem, copy4);
        k_copy4<<<copy4 / 256, 256>>>((const float4*)core, (float4*)(xmem + layerF), copy4);

        k_wgemm<<<dim3(HD / 256, NROW / 128), 256, WG_SMEM>>>(
            core, Wq + (size_t)l * DM * HD, nullptr, qb, NROW, HD, DM, 0, 0);
        k_wgemm<<<dim3(2 * HD / 256, KROW / 128), 256, WG_SMEM>>>(
            xmem, Wkv + (size_t)l * DM * 2 * HD, nullptr, kvb, KROW, 2 * HD, DM, 0, 0);
        k_wgemm<<<dim3(HD / 256, KLEN / 128), 256, WG_SMEM>>>(
            pos, Wr + (size_t)l * DM * HD, nullptr, rkb, KLEN, HD, DM, 0, 0);

        k_attn_score<<<dim3(KLEN / 64, QLEN / 64, BSZ * NH), 256>>>(
            qb, kvb, rwb, ac, BSZ * 2 * HD, 2 * HD, 0);
        k_attn_score<<<dim3(KLEN / 64, QLEN / 64, BSZ * NH), 256>>>(
            qb, rkb, rrb, bd, HD, 0, 1);

        k_softmax<<<dim3(QLEN, BSZ * NH), 256>>>(ac, bd);
        k_attn_pv<<<dim3(QLEN / 64, BSZ * NH), 256>>>(ac, kvb, vec);

        k_wgemm<<<dim3(DM / 256, NROW / 128), 256, WG_SMEM>>>(
            vec, Wo + (size_t)l * HD * DM, nullptr, tmp, NROW, DM, HD, 0, 0);
        k_ln<<<NROW, 256>>>(core, tmp, ln1g + (size_t)l * DM, ln1b + (size_t)l * DM, core);

        k_wgemm<<<dim3(DI / 256, NROW / 128), 256, WG_SMEM>>>(
            core, W1 + (size_t)l * DM * DI, b1 + (size_t)l * DI, ffb, NROW, DI, DM, 0, 1);
        k_wgemm<<<dim3(DM / 256, NROW / 128), 256, WG_SMEM>>>(
            ffb, W2 + (size_t)l * DI * DM, b2 + (size_t)l * DM, tmp, NROW, DM, DI, 0, 0);
        k_ln<<<NROW, 256>>>(core, tmp, ln2g + (size_t)l * DM, ln2b + (size_t)l * DM, core);

        if (l < NLAYER - 1 && lossN + (size_t)(l + 2) * layerF <= outN)
            k_copy4<<<copy4 / 256, 256>>>((const float4*)core,
                                          (float4*)(mems_out + (size_t)(l + 1) * layerF), copy4);
    }

    k_wgemm<<<dim3(VOCAB / 256, NROW / 128), 256, WG_SMEM>>>(
        core, embW, nullptr, lg, NROW, VOCAB, DM, 1, 0);
    k_loss<<<NROW, 256>>>(lg, target, loss_out);
}